// round 4
// baseline (speedup 1.0000x reference)
#include <cuda_runtime.h>
#include <cstdint>

// unpool expand: out quad [4i,4i+4) owned by input i;
//   out[4i + (idx[i]&3)] = in[i], other lanes 0.
// idx is int32. n = 8,388,608.
//
// Each thread owns 4 PAIRS of consecutive elements (8 elems total),
// pair-block-stride so all loads (int2/float2) and 256-bit stores stay
// min-density coalesced. st.global.v8.f32 = Blackwell STG.E.256.

#define PAIRS_PER_THREAD 4
#define THREADS 256

__device__ __forceinline__ void stg_v8(float* p,
                                       float a0, float a1, float a2, float a3,
                                       float a4, float a5, float a6, float a7)
{
    asm volatile(
        "st.global.v8.f32 [%0], {%1, %2, %3, %4, %5, %6, %7, %8};"
        :: "l"(p),
           "f"(a0), "f"(a1), "f"(a2), "f"(a3),
           "f"(a4), "f"(a5), "f"(a6), "f"(a7)
        : "memory");
}

__global__ void __launch_bounds__(THREADS)
unpool_expand_kernel(const float2* __restrict__ in2,
                     const int2* __restrict__ idx2,
                     float* __restrict__ out,
                     int n_pairs)
{
    int base = blockIdx.x * (THREADS * PAIRS_PER_THREAD) + threadIdx.x;

    int2   id[PAIRS_PER_THREAD];
    float2 v[PAIRS_PER_THREAD];

    // Front-batched independent loads: 8 x 8B in flight per thread.
#pragma unroll
    for (int k = 0; k < PAIRS_PER_THREAD; k++) {
        int j = base + k * THREADS;
        id[k] = __ldg(idx2 + j);
        v[k]  = __ldg(in2 + j);
    }

#pragma unroll
    for (int k = 0; k < PAIRS_PER_THREAD; k++) {
        int j = base + k * THREADS;
        float q[8] = {0.f, 0.f, 0.f, 0.f, 0.f, 0.f, 0.f, 0.f};
        q[id[k].x & 3]       = v[k].x;   // quad for element 2j
        q[(id[k].y & 3) + 4] = v[k].y;   // quad for element 2j+1
        // 32B store at byte offset 32*j — warp covers 1KB contiguous.
        stg_v8(out + 8 * (size_t)j,
               q[0], q[1], q[2], q[3], q[4], q[5], q[6], q[7]);
    }
}

extern "C" void kernel_launch(void* const* d_in, const int* in_sizes, int n_in,
                              void* d_out, int out_size)
{
    const float2* in2  = (const float2*)d_in[0];
    const int2*   idx2 = (const int2*)d_in[1];
    float*        out  = (float*)d_out;

    int n = in_sizes[0];          // 8,388,608
    int n_pairs = n / 2;          // 4,194,304 = 4096 * 1024, exact
    int blocks = n_pairs / (THREADS * PAIRS_PER_THREAD);
    unpool_expand_kernel<<<blocks, THREADS>>>(in2, idx2, out, n_pairs);
}